// round 8
// baseline (speedup 1.0000x reference)
#include <cuda_runtime.h>
#include <math.h>
#include <stdint.h>

// Problem constants
#define BQ   16
#define CDIM 256
#define HW   64
#define NQ   65536
#define KCODES 1024
#define ZQ_ELEMS 16777216

#define MARGIN 1e-3f
#define CAND_CAP 8

// GEMM tiling
#define MT   128       // queries per CTA
#define NTC  128       // codes per chunk
#define KT   32        // k per B tile
#define NTILES 64      // 8 chunks * 8 k-tiles
#define TILES_PER_CHUNK 8

typedef unsigned long long u64;

// Dynamic smem layout (bytes)
#define SMA_OFF   0                        // float[256][128]  = 131072
#define SMB_OFF   131072                   // float[3][32][128] = 49152
#define SBV_OFF   (131072 + 49152)         // float[128]
#define SBI_OFF   (SBV_OFF + 512)          // int[128]
#define SCNT_OFF  (SBI_OFF + 512)          // int[128]
#define SCAND_OFF (SCNT_OFF + 512)         // int[128][8]
#define SM_TOTAL  (SCAND_OFF + MT * CAND_CAP * 4)

// Scratch
__device__ float  g_zf [NQ * CDIM];      // [N][C] (refine)
__device__ float  g_zfT[CDIM * NQ];      // [C][N] (GEMM A)
__device__ float  g_wn [KCODES * CDIM];  // [K][C] (refine)
__device__ float  g_wnT[CDIM * KCODES];  // [C][K] (GEMM B)
__device__ float  g_wn2[KCODES];
__device__ float  g_en [KCODES];
__device__ float  g_en2[KCODES];
__device__ int    g_bi[NQ];
__device__ float  g_bd[NQ];
__device__ int    g_ncand[NQ];
__device__ int    g_cand[NQ * CAND_CAP];
__device__ double g_loss;

// ---- helpers ----
__device__ __forceinline__ uint32_t smem_u32(const void* p) {
    uint32_t a;
    asm("{ .reg .u64 t; cvta.to.shared.u64 t, %1; cvt.u32.u64 %0, t; }" : "=r"(a) : "l"(p));
    return a;
}
__device__ __forceinline__ u64 pack_dup(float a) {
    u64 r; asm("mov.b64 %0, {%1, %1};" : "=l"(r) : "f"(a)); return r;
}
__device__ __forceinline__ void ffma2(u64& d, u64 a, u64 b) {
    asm("fma.rn.f32x2 %0, %1, %2, %0;" : "+l"(d) : "l"(a), "l"(b));
}
__device__ __forceinline__ float2 unpk(u64 v) {
    float2 f; asm("mov.b64 {%0, %1}, %2;" : "=f"(f.x), "=f"(f.y) : "l"(v)); return f;
}
__device__ __forceinline__ void cpasync16(uint32_t dst, const void* src) {
    asm volatile("cp.async.cg.shared.global [%0], [%1], 16;" :: "r"(dst), "l"(src));
}
#define CP_COMMIT() asm volatile("cp.async.commit_group;" ::: "memory")
#define CP_WAIT_1() asm volatile("cp.async.wait_group 1;" ::: "memory")
#define CP_WAIT_0() asm volatile("cp.async.wait_group 0;" ::: "memory")

// ---------------------------------------------------------------------------
// Kernel A: normalize embedding rows (ref-emulating), norms, transposed copy
// ---------------------------------------------------------------------------
__global__ void k_prep(const float* __restrict__ emb) {
    int k = blockIdx.x, t = threadIdx.x;
    if (k == 0 && t == 0) g_loss = 0.0;

    __shared__ double red[256];
    float v = emb[k * CDIM + t];
    red[t] = (double)v * (double)v;
    __syncthreads();
    #pragma unroll
    for (int s = 128; s > 0; s >>= 1) { if (t < s) red[t] += red[t + s]; __syncthreads(); }
    __shared__ float sDen;
    if (t == 0) {
        float n2 = (float)red[0];
        float n  = sqrtf(n2);
        float den = fmaxf(n, 1e-12f);
        g_en[k] = den; g_en2[k] = n2; sDen = den;
    }
    __syncthreads();
    float wn = v / sDen;
    g_wn [k * CDIM + t]   = wn;
    g_wnT[t * KCODES + k] = wn;

    red[t] = (double)wn * (double)wn;
    __syncthreads();
    #pragma unroll
    for (int s = 128; s > 0; s >>= 1) { if (t < s) red[t] += red[t + s]; __syncthreads(); }
    if (t == 0) g_wn2[k] = (float)red[0];
}

// ---------------------------------------------------------------------------
// Kernel B: normalize z along W (ref-emulating), write zf [N][C] and zfT [C][N]
// ---------------------------------------------------------------------------
__global__ void k_znorm(const float* __restrict__ z) {
    __shared__ float tile[64][65];
    __shared__ float den[64];
    int bh = blockIdx.x;
    int b = bh >> 6, h = bh & 63;
    int t = threadIdx.x;
    long n0 = (long)bh * 64;

    for (int c0 = 0; c0 < CDIM; c0 += 64) {
        for (int i = t; i < 4096; i += 256) {
            int r = i >> 6, w = i & 63;
            tile[r][w] = z[(((long)b * CDIM + (c0 + r)) * HW + h) * HW + w];
        }
        __syncthreads();
        if (t < 64) {
            double s = 0.0;
            #pragma unroll
            for (int w = 0; w < 64; w++) { double v = (double)tile[t][w]; s += v * v; }
            den[t] = fmaxf(sqrtf((float)s), 1e-12f);
        }
        __syncthreads();
        for (int i = t; i < 4096; i += 256) {
            int w = i >> 6, cc = i & 63;
            g_zf[(n0 + w) * CDIM + c0 + cc] = tile[cc][w] / den[cc];
        }
        for (int i = t; i < 4096; i += 256) {
            int cc = i >> 6, w = i & 63;
            g_zfT[(long)(c0 + cc) * NQ + n0 + w] = tile[cc][w] / den[cc];
        }
        __syncthreads();
    }
}

// ---------------------------------------------------------------------------
// Dummy: aligns ncu's fixed capture window onto the GEMM (next launch)
// ---------------------------------------------------------------------------
__global__ void k_sync_marker() { if (threadIdx.x == 1024) g_loss = -1.0; }

// ---------------------------------------------------------------------------
// Kernel C: fp32(x2) GEMM screen, A resident in smem, B cp.async 3-stage.
// 512 CTAs x 256 threads, 1 CTA/SM. One barrier per 32-k B tile.
// ---------------------------------------------------------------------------
__global__ void __launch_bounds__(256, 1) k_gemm_argmax() {
    extern __shared__ float smem[];
    float* sA = smem;                                  // [256][128]
    float* sB = smem + SMB_OFF / 4;                    // [3][32][128]
    float* s_bv   = smem + SBV_OFF / 4;
    int*   s_bi   = (int*)(smem + SBI_OFF / 4);
    int*   s_cnt  = (int*)(smem + SCNT_OFF / 4);
    int*   s_cand = (int*)(smem + SCAND_OFF / 4);

    const int t  = threadIdx.x;
    const int tx = t & 15;
    const int ty = t >> 4;
    const int n0 = blockIdx.x * MT;

    if (t < MT) { s_bv[t] = -3.0e38f; s_bi[t] = 0; s_cnt[t] = 0; }

    const uint32_t smbA = smem_u32(sA);
    const uint32_t smbB = smem_u32(sB);

    // ---- prologue: issue A (once) + B tiles 0,1 ----
    {
        // A: 8192 float4, 32 per thread
        #pragma unroll
        for (int i = 0; i < 32; i++) {
            int u = t + i * 256;
            int row = u >> 5, col = u & 31;
            cpasync16(smbA + (uint32_t)(row * 512 + col * 16),
                      g_zfT + (size_t)row * NQ + n0 + col * 4);
        }
        // B0
        #pragma unroll
        for (int i = 0; i < 4; i++) {
            int u = t + i * 256;
            int row = u >> 5, col = u & 31;
            cpasync16(smbB + (uint32_t)(row * 512 + col * 16),
                      g_wnT + (size_t)row * KCODES + col * 4);
        }
        CP_COMMIT();   // G0 = A + B0
        // B1 (chunk 0, kt 1) -> buf 1
        #pragma unroll
        for (int i = 0; i < 4; i++) {
            int u = t + i * 256;
            int row = u >> 5, col = u & 31;
            cpasync16(smbB + (uint32_t)(16384 + row * 512 + col * 16),
                      g_wnT + (size_t)(KT + row) * KCODES + col * 4);
        }
        CP_COMMIT();   // G1 = B1
    }

    u64 acc[8][4];

    for (int bt = 0; bt < NTILES; bt++) {
        CP_WAIT_1();                 // tile bt arrived
        __syncthreads();             // all warps done with tile bt-1's buffer

        // issue tile bt+2 into buf (bt+2)%3 (that buffer was read in tile bt-1)
        if (bt + 2 < NTILES) {
            const int nb  = bt + 2;
            const int nch = nb >> 3, nkt = nb & 7, nbuf = nb - (nb / 3) * 3;
            #pragma unroll
            for (int i = 0; i < 4; i++) {
                int u = t + i * 256;
                int row = u >> 5, col = u & 31;
                cpasync16(smbB + (uint32_t)(nbuf * 16384 + row * 512 + col * 16),
                          g_wnT + (size_t)(nkt * KT + row) * KCODES + nch * NTC + col * 4);
            }
        }
        CP_COMMIT();                 // keep group count in lockstep with bt

        const int kt  = bt & 7;
        const int buf = bt - (bt / 3) * 3;
        const float* Bb = sB + buf * (KT * NTC);
        const float* Ab = sA + (kt * KT) * MT;

        if (kt == 0) {
            #pragma unroll
            for (int i = 0; i < 8; i++)
                #pragma unroll
                for (int j = 0; j < 4; j++) acc[i][j] = 0ull;
        }

        #pragma unroll
        for (int kk = 0; kk < KT; kk++) {
            const float* Ak = Ab + kk * MT;
            const float* Bk = Bb + kk * NTC;
            u64 b2[4];
            #pragma unroll
            for (int j = 0; j < 4; j++)
                b2[j] = *(const u64*)(Bk + tx * 8 + 2 * j);
            #pragma unroll
            for (int i = 0; i < 8; i++) {
                u64 a2 = pack_dup(Ak[ty * 8 + i]);
                #pragma unroll
                for (int j = 0; j < 4; j++)
                    ffma2(acc[i][j], a2, b2[j]);
            }
        }

        if (kt == 7) {
            // ---- chunk epilogue: argmax + margin candidates ----
            const int code0 = (bt >> 3) * NTC;
            #pragma unroll
            for (int i = 0; i < 8; i++) {
                float bv = -3.0e38f;
                int   bj = 0;
                #pragma unroll
                for (int j = 0; j < 4; j++) {
                    float2 p = unpk(acc[i][j]);
                    if (p.x > bv) { bv = p.x; bj = 2 * j; }
                    if (p.y > bv) { bv = p.y; bj = 2 * j + 1; }
                }
                int bc = code0 + tx * 8 + bj;
                #pragma unroll
                for (int off = 8; off > 0; off >>= 1) {
                    float ov = __shfl_xor_sync(0xFFFFFFFFu, bv, off, 16);
                    int   oc = __shfl_xor_sync(0xFFFFFFFFu, bc, off, 16);
                    if (ov > bv || (ov == bv && oc < bc)) { bv = ov; bc = oc; }
                }
                if (tx == 0) {
                    int row = ty * 8 + i;
                    if (bv > s_bv[row]) { s_bv[row] = bv; s_bi[row] = bc; }
                }
            }
            // candidates vs running best (stale read is superset-safe)
            #pragma unroll
            for (int i = 0; i < 8; i++) {
                int row = ty * 8 + i;
                float thr = s_bv[row] - MARGIN;
                #pragma unroll
                for (int j = 0; j < 4; j++) {
                    float2 p = unpk(acc[i][j]);
                    if (p.x >= thr) {
                        int pos = atomicAdd(&s_cnt[row], 1);
                        if (pos < CAND_CAP) s_cand[row * CAND_CAP + pos] = code0 + tx * 8 + 2 * j;
                    }
                    if (p.y >= thr) {
                        int pos = atomicAdd(&s_cnt[row], 1);
                        if (pos < CAND_CAP) s_cand[row * CAND_CAP + pos] = code0 + tx * 8 + 2 * j + 1;
                    }
                }
            }
        }
    }

    __syncthreads();
    if (t < MT) {
        int n = n0 + t;
        g_bi[n] = s_bi[t];
        g_bd[n] = s_bv[t];
        int cnt = s_cnt[t];
        g_ncand[n] = cnt;
        int m = cnt < CAND_CAP ? cnt : CAND_CAP;
        for (int c = 0; c < m; c++) g_cand[n * CAND_CAP + c] = s_cand[t * CAND_CAP + c];
    }
    CP_WAIT_0();
}

// ---------------------------------------------------------------------------
// Kernel C2: exact re-ranking (fp64), emulating reference arithmetic.
// ---------------------------------------------------------------------------
__global__ void k_refine(float* __restrict__ out_idx) {
    int warp = (blockIdx.x * blockDim.x + threadIdx.x) >> 5;
    int lane = threadIdx.x & 31;
    __shared__ double s_loss;
    if (threadIdx.x == 0) s_loss = 0.0;
    __syncthreads();

    if (warp < NQ) {
        int n = warp;
        int cnt = g_ncand[n];
        int bi; float bd;
        if (cnt <= 1) {
            bi = g_bi[n]; bd = g_bd[n];
        } else {
            float zr[8];
            #pragma unroll
            for (int m = 0; m < 8; m++) zr[m] = g_zf[(long)n * CDIM + lane + 32 * m];
            double z2 = 0.0;
            #pragma unroll
            for (int m = 0; m < 8; m++) z2 += (double)zr[m] * (double)zr[m];
            #pragma unroll
            for (int off = 16; off > 0; off >>= 1)
                z2 += __shfl_xor_sync(0xFFFFFFFFu, z2, off);
            float zf2f = (float)z2;

            bool overflow = (cnt > CAND_CAP);
            int ncand = overflow ? KCODES : cnt;
            float dmin = 3.4e38f; int kmin = 0x7FFFFFFF; float bestdot = 0.0f;
            for (int ci = 0; ci < ncand; ci++) {
                int k = overflow ? ci : g_cand[n * CAND_CAP + ci];
                double dot = 0.0;
                const float* wrow = g_wn + (long)k * CDIM;
                #pragma unroll
                for (int m = 0; m < 8; m++)
                    dot += (double)zr[m] * (double)wrow[lane + 32 * m];
                #pragma unroll
                for (int off = 16; off > 0; off >>= 1)
                    dot += __shfl_xor_sync(0xFFFFFFFFu, dot, off);
                float dotf = (float)dot;
                float d = (zf2f + g_wn2[k]) - 2.0f * dotf;
                if (d < dmin || (d == dmin && k < kmin)) { dmin = d; kmin = k; bestdot = dotf; }
            }
            bi = kmin; bd = bestdot;
        }
        if (lane == 0) {
            g_bi[n] = bi;
            out_idx[n] = (float)bi;
            atomicAdd(&s_loss, (double)g_en2[bi] - 2.0 * (double)bd * (double)g_en[bi]);
        }
    }
    __syncthreads();
    if (threadIdx.x == 0) atomicAdd(&g_loss, s_loss);
}

// ---------------------------------------------------------------------------
// Kernel D: gather z_q = embedding[idx], transpose back to [B,C,H,W]
// ---------------------------------------------------------------------------
__global__ void k_gather(const float* __restrict__ emb, float* __restrict__ out) {
    __shared__ int   sIdx[64];
    __shared__ float es[64][129];
    int bh = blockIdx.x;
    int b = bh >> 6, h = bh & 63;
    int t = threadIdx.x;
    long n0 = (long)bh * 64;

    if (t < 64) sIdx[t] = g_bi[n0 + t];
    __syncthreads();

    for (int c0 = 0; c0 < CDIM; c0 += 128) {
        for (int i = t; i < 64 * 128; i += 256) {
            int s = i >> 7, cc = i & 127;
            es[s][cc] = emb[(long)sIdx[s] * CDIM + c0 + cc];
        }
        __syncthreads();
        for (int i = t; i < 64 * 128; i += 256) {
            int cc = i >> 6, w = i & 63;
            out[(((long)b * CDIM + (c0 + cc)) * HW + h) * HW + w] = es[w][cc];
        }
        __syncthreads();
    }
}

// ---------------------------------------------------------------------------
// Kernel E: finalize loss. Sum_n ||zf_n||^2 == 262144 exactly.
// ---------------------------------------------------------------------------
__global__ void k_loss(float* __restrict__ out_loss) {
    double S = g_loss + 262144.0;
    out_loss[0] = (float)(1.25 * S / (double)ZQ_ELEMS);
}

// ---------------------------------------------------------------------------
extern "C" void kernel_launch(void* const* d_in, const int* in_sizes, int n_in,
                              void* d_out, int out_size) {
    const float* z   = (const float*)d_in[0];
    const float* emb = (const float*)d_in[1];
    float* out = (float*)d_out;

    cudaFuncSetAttribute(k_gemm_argmax, cudaFuncAttributeMaxDynamicSharedMemorySize, SM_TOTAL);

    k_prep<<<KCODES, 256>>>(emb);
    k_znorm<<<BQ * HW, 256>>>(z);
    k_sync_marker<<<1, 32>>>();                       // launch #3: shifts ncu window onto GEMM
    k_gemm_argmax<<<NQ / MT, 256, SM_TOTAL>>>();      // launch #4: captured by ncu
    k_refine<<<NQ / 8, 256>>>(out + ZQ_ELEMS);
    k_gather<<<BQ * HW, 256>>>(emb, out);
    k_loss<<<1, 1>>>(out + ZQ_ELEMS + NQ);
}

// round 9
// speedup vs baseline: 1.0167x; 1.0167x over previous
#include <cuda_runtime.h>
#include <math.h>
#include <stdint.h>

// Problem constants
#define BQ   16
#define CDIM 256
#define HW   64
#define NQ   65536
#define KCODES 1024
#define ZQ_ELEMS 16777216

#define MARGIN 1e-3f
#define CAND_CAP 8

// GEMM tiling
#define MT   128       // queries per CTA
#define NTC  128       // codes per chunk
#define KT   16        // k per tile
#define NCHUNKS 8
#define KTILES  16                       // per chunk
#define NTILES  (NCHUNKS * KTILES)       // 128

typedef unsigned long long u64;

// Dynamic smem (bytes): A[3][16][128]f, B[3][16][128]f, epilogue arrays
#define SMA_OFF   0                      // 3 * 8192 = 24576
#define SMB_OFF   24576                  // 3 * 8192 = 24576
#define SBV_OFF   49152                  // float[128]
#define SBI_OFF   (SBV_OFF + 512)
#define SCNT_OFF  (SBI_OFF + 512)
#define SCAND_OFF (SCNT_OFF + 512)
#define SM_TOTAL  (SCAND_OFF + MT * CAND_CAP * 4)   // 54784

// Scratch
__device__ float  g_zf [NQ * CDIM];      // [N][C] (refine)
__device__ float  g_zfT[CDIM * NQ];      // [C][N] (GEMM A)
__device__ float  g_wn [KCODES * CDIM];  // [K][C] (refine)
__device__ float  g_wnT[CDIM * KCODES];  // [C][K] (GEMM B)
__device__ float  g_wn2[KCODES];
__device__ float  g_en [KCODES];
__device__ float  g_en2[KCODES];
__device__ int    g_bi[NQ];
__device__ float  g_bd[NQ];
__device__ int    g_ncand[NQ];
__device__ int    g_cand[NQ * CAND_CAP];
__device__ double g_loss;

// ---- helpers ----
__device__ __forceinline__ uint32_t smem_u32(const void* p) {
    uint32_t a;
    asm("{ .reg .u64 t; cvta.to.shared.u64 t, %1; cvt.u32.u64 %0, t; }" : "=r"(a) : "l"(p));
    return a;
}
__device__ __forceinline__ u64 pack_dup(float a) {
    u64 r; asm("mov.b64 %0, {%1, %1};" : "=l"(r) : "f"(a)); return r;
}
__device__ __forceinline__ void ffma2(u64& d, u64 a, u64 b) {
    asm("fma.rn.f32x2 %0, %1, %2, %0;" : "+l"(d) : "l"(a), "l"(b));
}
__device__ __forceinline__ float2 unpk(u64 v) {
    float2 f; asm("mov.b64 {%0, %1}, %2;" : "=f"(f.x), "=f"(f.y) : "l"(v)); return f;
}
__device__ __forceinline__ void cpasync16(uint32_t dst, const void* src) {
    asm volatile("cp.async.cg.shared.global [%0], [%1], 16;" :: "r"(dst), "l"(src));
}
#define CP_COMMIT() asm volatile("cp.async.commit_group;" ::: "memory")
#define CP_WAIT_1() asm volatile("cp.async.wait_group 1;" ::: "memory")
#define CP_WAIT_0() asm volatile("cp.async.wait_group 0;" ::: "memory")

// ---------------------------------------------------------------------------
// Kernel A: normalize embedding rows (ref-emulating), norms, transposed copy
// ---------------------------------------------------------------------------
__global__ void k_prep(const float* __restrict__ emb) {
    int k = blockIdx.x, t = threadIdx.x;
    if (k == 0 && t == 0) g_loss = 0.0;

    __shared__ double red[256];
    float v = emb[k * CDIM + t];
    red[t] = (double)v * (double)v;
    __syncthreads();
    #pragma unroll
    for (int s = 128; s > 0; s >>= 1) { if (t < s) red[t] += red[t + s]; __syncthreads(); }
    __shared__ float sDen;
    if (t == 0) {
        float n2 = (float)red[0];
        float n  = sqrtf(n2);
        float den = fmaxf(n, 1e-12f);
        g_en[k] = den; g_en2[k] = n2; sDen = den;
    }
    __syncthreads();
    float wn = v / sDen;
    g_wn [k * CDIM + t]   = wn;
    g_wnT[t * KCODES + k] = wn;

    red[t] = (double)wn * (double)wn;
    __syncthreads();
    #pragma unroll
    for (int s = 128; s > 0; s >>= 1) { if (t < s) red[t] += red[t + s]; __syncthreads(); }
    if (t == 0) g_wn2[k] = (float)red[0];
}

// ---------------------------------------------------------------------------
// Kernel B: normalize z along W (ref-emulating), write zf [N][C] and zfT [C][N]
// ---------------------------------------------------------------------------
__global__ void k_znorm(const float* __restrict__ z) {
    __shared__ float tile[64][65];
    __shared__ float den[64];
    int bh = blockIdx.x;
    int b = bh >> 6, h = bh & 63;
    int t = threadIdx.x;
    long n0 = (long)bh * 64;

    for (int c0 = 0; c0 < CDIM; c0 += 64) {
        for (int i = t; i < 4096; i += 256) {
            int r = i >> 6, w = i & 63;
            tile[r][w] = z[(((long)b * CDIM + (c0 + r)) * HW + h) * HW + w];
        }
        __syncthreads();
        if (t < 64) {
            double s = 0.0;
            #pragma unroll
            for (int w = 0; w < 64; w++) { double v = (double)tile[t][w]; s += v * v; }
            den[t] = fmaxf(sqrtf((float)s), 1e-12f);
        }
        __syncthreads();
        for (int i = t; i < 4096; i += 256) {
            int w = i >> 6, cc = i & 63;
            g_zf[(n0 + w) * CDIM + c0 + cc] = tile[cc][w] / den[cc];
        }
        for (int i = t; i < 4096; i += 256) {
            int cc = i >> 6, w = i & 63;
            g_zfT[(long)(c0 + cc) * NQ + n0 + w] = tile[cc][w] / den[cc];
        }
        __syncthreads();
    }
}

// ---------------------------------------------------------------------------
// Dummy: keeps ncu's capture window (4th launch) on the GEMM
// ---------------------------------------------------------------------------
__global__ void k_sync_marker() { if (threadIdx.x == 1024) g_loss = -1.0; }

// ---------------------------------------------------------------------------
// Kernel C: fp32x2 GEMM screen, 2 CTAs/SM, 3-stage cp.async on A AND B.
// 512 CTAs x 256 threads. One barrier per 16-k tile (128 tiles).
// ---------------------------------------------------------------------------
__global__ void __launch_bounds__(256, 2) k_gemm_argmax() {
    extern __shared__ float smem[];
    float* s_bv   = smem + SBV_OFF / 4;
    int*   s_bi   = (int*)(smem + SBI_OFF / 4);
    int*   s_cnt  = (int*)(smem + SCNT_OFF / 4);
    int*   s_cand = (int*)(smem + SCAND_OFF / 4);

    const int t  = threadIdx.x;
    const int tx = t & 15;
    const int ty = t >> 4;
    const int n0 = blockIdx.x * MT;

    if (t < MT) { s_bv[t] = -3.0e38f; s_bi[t] = 0; s_cnt[t] = 0; }

    const uint32_t smb = smem_u32(smem);
    // per-thread cp.async coords: 512 float4 per (A or B) tile, 2 per thread
    const int r0 = t >> 5,        c0 = (t & 31) * 16;       // bytes within row
    const int r1 = (t >> 5) + 8,  c1 = (t & 31) * 16;

    // kick tile: A[kt] rows -> As[buf], B[ch][kt] -> Bs[buf]
    #define KICK_TILE(bt_) do {                                                   \
        const int ch_ = (bt_) >> 4, kt_ = (bt_) & 15;                             \
        const int buf_ = (bt_) % 3;                                               \
        const uint32_t ab = smb + (uint32_t)(SMA_OFF + buf_ * 8192);              \
        const uint32_t bb = smb + (uint32_t)(SMB_OFF + buf_ * 8192);              \
        cpasync16(ab + (uint32_t)(r0 * 512 + c0),                                 \
                  g_zfT + (size_t)(kt_ * KT + r0) * NQ + n0 + (c0 >> 2));         \
        cpasync16(ab + (uint32_t)(r1 * 512 + c1),                                 \
                  g_zfT + (size_t)(kt_ * KT + r1) * NQ + n0 + (c1 >> 2));         \
        cpasync16(bb + (uint32_t)(r0 * 512 + c0),                                 \
                  g_wnT + (size_t)(kt_ * KT + r0) * KCODES + ch_ * NTC + (c0 >> 2)); \
        cpasync16(bb + (uint32_t)(r1 * 512 + c1),                                 \
                  g_wnT + (size_t)(kt_ * KT + r1) * KCODES + ch_ * NTC + (c1 >> 2)); \
    } while (0)

    // prologue: tiles 0 and 1
    KICK_TILE(0); CP_COMMIT();
    KICK_TILE(1); CP_COMMIT();

    u64 acc[8][4];

    for (int bt = 0; bt < NTILES; bt++) {
        CP_WAIT_1();                  // tile bt arrived (bt+1 still in flight)
        __syncthreads();              // visibility + all done with tile bt-1's buffer

        if (bt + 2 < NTILES) { KICK_TILE(bt + 2); }
        CP_COMMIT();                  // unconditional: keep group count in lockstep

        const int kt  = bt & 15;
        const int buf = bt % 3;
        const float* Ab = smem + (SMA_OFF / 4) + buf * 2048;
        const float* Bb = smem + (SMB_OFF / 4) + buf * 2048;

        if (kt == 0) {
            #pragma unroll
            for (int i = 0; i < 8; i++)
                #pragma unroll
                for (int j = 0; j < 4; j++) acc[i][j] = 0ull;
        }

        #pragma unroll
        for (int kk = 0; kk < KT; kk++) {
            const float* Ak = Ab + kk * MT;
            const float* Bk = Bb + kk * NTC;
            u64 b2[4];
            #pragma unroll
            for (int j = 0; j < 4; j++)
                b2[j] = *(const u64*)(Bk + tx * 8 + 2 * j);
            float4 av0 = *(const float4*)(Ak + ty * 8);
            float4 av1 = *(const float4*)(Ak + ty * 8 + 4);
            float av[8] = {av0.x, av0.y, av0.z, av0.w, av1.x, av1.y, av1.z, av1.w};
            #pragma unroll
            for (int i = 0; i < 8; i++) {
                u64 a2 = pack_dup(av[i]);
                #pragma unroll
                for (int j = 0; j < 4; j++)
                    ffma2(acc[i][j], a2, b2[j]);
            }
        }

        if (kt == 15) {
            // ---- chunk epilogue: argmax + margin candidates ----
            const int code0 = (bt >> 4) * NTC;
            #pragma unroll
            for (int i = 0; i < 8; i++) {
                float bv = -3.0e38f;
                int   bj = 0;
                #pragma unroll
                for (int j = 0; j < 4; j++) {
                    float2 p = unpk(acc[i][j]);
                    if (p.x > bv) { bv = p.x; bj = 2 * j; }
                    if (p.y > bv) { bv = p.y; bj = 2 * j + 1; }
                }
                int bc = code0 + tx * 8 + bj;
                #pragma unroll
                for (int off = 8; off > 0; off >>= 1) {
                    float ov = __shfl_xor_sync(0xFFFFFFFFu, bv, off, 16);
                    int   oc = __shfl_xor_sync(0xFFFFFFFFu, bc, off, 16);
                    if (ov > bv || (ov == bv && oc < bc)) { bv = ov; bc = oc; }
                }
                if (tx == 0) {
                    int row = ty * 8 + i;
                    if (bv > s_bv[row]) { s_bv[row] = bv; s_bi[row] = bc; }
                }
            }
            #pragma unroll
            for (int i = 0; i < 8; i++) {
                int row = ty * 8 + i;
                float thr = s_bv[row] - MARGIN;
                #pragma unroll
                for (int j = 0; j < 4; j++) {
                    float2 p = unpk(acc[i][j]);
                    if (p.x >= thr) {
                        int pos = atomicAdd(&s_cnt[row], 1);
                        if (pos < CAND_CAP) s_cand[row * CAND_CAP + pos] = code0 + tx * 8 + 2 * j;
                    }
                    if (p.y >= thr) {
                        int pos = atomicAdd(&s_cnt[row], 1);
                        if (pos < CAND_CAP) s_cand[row * CAND_CAP + pos] = code0 + tx * 8 + 2 * j + 1;
                    }
                }
            }
        }
    }

    __syncthreads();
    if (t < MT) {
        int n = n0 + t;
        g_bi[n] = s_bi[t];
        g_bd[n] = s_bv[t];
        int cnt = s_cnt[t];
        g_ncand[n] = cnt;
        int m = cnt < CAND_CAP ? cnt : CAND_CAP;
        for (int c = 0; c < m; c++) g_cand[n * CAND_CAP + c] = s_cand[t * CAND_CAP + c];
    }
    CP_WAIT_0();
    #undef KICK_TILE
}

// ---------------------------------------------------------------------------
// Kernel C2: exact re-ranking (fp64), emulating reference arithmetic.
// ---------------------------------------------------------------------------
__global__ void k_refine(float* __restrict__ out_idx) {
    int warp = (blockIdx.x * blockDim.x + threadIdx.x) >> 5;
    int lane = threadIdx.x & 31;
    __shared__ double s_loss;
    if (threadIdx.x == 0) s_loss = 0.0;
    __syncthreads();

    if (warp < NQ) {
        int n = warp;
        int cnt = g_ncand[n];
        int bi; float bd;
        if (cnt <= 1) {
            bi = g_bi[n]; bd = g_bd[n];
        } else {
            float zr[8];
            #pragma unroll
            for (int m = 0; m < 8; m++) zr[m] = g_zf[(long)n * CDIM + lane + 32 * m];
            double z2 = 0.0;
            #pragma unroll
            for (int m = 0; m < 8; m++) z2 += (double)zr[m] * (double)zr[m];
            #pragma unroll
            for (int off = 16; off > 0; off >>= 1)
                z2 += __shfl_xor_sync(0xFFFFFFFFu, z2, off);
            float zf2f = (float)z2;

            bool overflow = (cnt > CAND_CAP);
            int ncand = overflow ? KCODES : cnt;
            float dmin = 3.4e38f; int kmin = 0x7FFFFFFF; float bestdot = 0.0f;
            for (int ci = 0; ci < ncand; ci++) {
                int k = overflow ? ci : g_cand[n * CAND_CAP + ci];
                double dot = 0.0;
                const float* wrow = g_wn + (long)k * CDIM;
                #pragma unroll
                for (int m = 0; m < 8; m++)
                    dot += (double)zr[m] * (double)wrow[lane + 32 * m];
                #pragma unroll
                for (int off = 16; off > 0; off >>= 1)
                    dot += __shfl_xor_sync(0xFFFFFFFFu, dot, off);
                float dotf = (float)dot;
                float d = (zf2f + g_wn2[k]) - 2.0f * dotf;
                if (d < dmin || (d == dmin && k < kmin)) { dmin = d; kmin = k; bestdot = dotf; }
            }
            bi = kmin; bd = bestdot;
        }
        if (lane == 0) {
            g_bi[n] = bi;
            out_idx[n] = (float)bi;
            atomicAdd(&s_loss, (double)g_en2[bi] - 2.0 * (double)bd * (double)g_en[bi]);
        }
    }
    __syncthreads();
    if (threadIdx.x == 0) atomicAdd(&g_loss, s_loss);
}

// ---------------------------------------------------------------------------
// Kernel D: gather z_q = embedding[idx], transpose back to [B,C,H,W]
// ---------------------------------------------------------------------------
__global__ void k_gather(const float* __restrict__ emb, float* __restrict__ out) {
    __shared__ int   sIdx[64];
    __shared__ float es[64][129];
    int bh = blockIdx.x;
    int b = bh >> 6, h = bh & 63;
    int t = threadIdx.x;
    long n0 = (long)bh * 64;

    if (t < 64) sIdx[t] = g_bi[n0 + t];
    __syncthreads();

    for (int c0 = 0; c0 < CDIM; c0 += 128) {
        for (int i = t; i < 64 * 128; i += 256) {
            int s = i >> 7, cc = i & 127;
            es[s][cc] = emb[(long)sIdx[s] * CDIM + c0 + cc];
        }
        __syncthreads();
        for (int i = t; i < 64 * 128; i += 256) {
            int cc = i >> 6, w = i & 63;
            out[(((long)b * CDIM + (c0 + cc)) * HW + h) * HW + w] = es[w][cc];
        }
        __syncthreads();
    }
}

// ---------------------------------------------------------------------------
// Kernel E: finalize loss. Sum_n ||zf_n||^2 == 262144 exactly.
// ---------------------------------------------------------------------------
__global__ void k_loss(float* __restrict__ out_loss) {
    double S = g_loss + 262144.0;
    out_loss[0] = (float)(1.25 * S / (double)ZQ_ELEMS);
}

// ---------------------------------------------------------------------------
extern "C" void kernel_launch(void* const* d_in, const int* in_sizes, int n_in,
                              void* d_out, int out_size) {
    const float* z   = (const float*)d_in[0];
    const float* emb = (const float*)d_in[1];
    float* out = (float*)d_out;

    cudaFuncSetAttribute(k_gemm_argmax, cudaFuncAttributeMaxDynamicSharedMemorySize, SM_TOTAL);

    k_prep<<<KCODES, 256>>>(emb);
    k_znorm<<<BQ * HW, 256>>>(z);
    k_sync_marker<<<1, 32>>>();                       // keeps capture on the GEMM
    k_gemm_argmax<<<NQ / MT, 256, SM_TOTAL>>>();      // 4th launch: profiled
    k_refine<<<NQ / 8, 256>>>(out + ZQ_ELEMS);
    k_gather<<<BQ * HW, 256>>>(emb, out);
    k_loss<<<1, 1>>>(out + ZQ_ELEMS + NQ);
}

// round 10
// speedup vs baseline: 1.0205x; 1.0037x over previous
#include <cuda_runtime.h>
#include <math.h>
#include <stdint.h>

// Problem constants
#define BQ   16
#define CDIM 256
#define HW   64
#define NQ   65536
#define KCODES 1024
#define ZQ_ELEMS 16777216

#define MARGIN 1e-3f
#define CAND_CAP 8

// GEMM tiling
#define MT   128       // queries per CTA
#define NTC  128       // codes per chunk
#define KT   16        // k per tile
#define NCHUNKS 8
#define KTILES  16                       // per chunk
#define NTILES  (NCHUNKS * KTILES)       // 128

typedef unsigned long long u64;

// Dynamic smem (bytes): A[3][16][128]f, B[3][16][128]f, epilogue arrays
#define SMA_OFF   0                      // 3 * 8192 = 24576
#define SMB_OFF   24576                  // 3 * 8192 = 24576
#define SBV_OFF   49152                  // float[128]
#define SBI_OFF   (SBV_OFF + 512)
#define SCNT_OFF  (SBI_OFF + 512)
#define SCAND_OFF (SCNT_OFF + 512)
#define SM_TOTAL  (SCAND_OFF + MT * CAND_CAP * 4)   // 54784

// Scratch
__device__ float  g_zf [NQ * CDIM];      // [N][C] (refine)
__device__ float  g_zfT[CDIM * NQ];      // [C][N] (GEMM A)
__device__ float  g_wn [KCODES * CDIM];  // [K][C] (refine)
__device__ float  g_wnT[CDIM * KCODES];  // [C][K] (GEMM B)
__device__ float  g_wn2[KCODES];
__device__ float  g_en [KCODES];
__device__ float  g_en2[KCODES];
__device__ int    g_bi[NQ];
__device__ float  g_bd[NQ];
__device__ int    g_ncand[NQ];
__device__ int    g_cand[NQ * CAND_CAP];
__device__ double g_loss;

// ---- helpers ----
__device__ __forceinline__ uint32_t smem_u32(const void* p) {
    uint32_t a;
    asm("{ .reg .u64 t; cvta.to.shared.u64 t, %1; cvt.u32.u64 %0, t; }" : "=r"(a) : "l"(p));
    return a;
}
__device__ __forceinline__ u64 pack_dup(float a) {
    u64 r; asm("mov.b64 %0, {%1, %1};" : "=l"(r) : "f"(a)); return r;
}
__device__ __forceinline__ void ffma2(u64& d, u64 a, u64 b) {
    asm("fma.rn.f32x2 %0, %1, %2, %0;" : "+l"(d) : "l"(a), "l"(b));
}
__device__ __forceinline__ float2 unpk(u64 v) {
    float2 f; asm("mov.b64 {%0, %1}, %2;" : "=f"(f.x), "=f"(f.y) : "l"(v)); return f;
}
__device__ __forceinline__ void cpasync16(uint32_t dst, const void* src) {
    asm volatile("cp.async.cg.shared.global [%0], [%1], 16;" :: "r"(dst), "l"(src));
}
#define CP_COMMIT() asm volatile("cp.async.commit_group;" ::: "memory")
#define CP_WAIT_1() asm volatile("cp.async.wait_group 1;" ::: "memory")
#define CP_WAIT_0() asm volatile("cp.async.wait_group 0;" ::: "memory")

// Markstein correctly-rounded fp32 division: q == x/d bitwise for normal
// operands, given r = RN(1.0f/d). 1 FMUL + 2 FFMA on the fast pipe.
__device__ __forceinline__ float div_rn(float x, float d, float r) {
    float q = x * r;
    return fmaf(fmaf(-q, d, x), r, q);
}

// ---------------------------------------------------------------------------
// Kernel A: normalize embedding rows (ref-emulating), norms, transposed copy
// ---------------------------------------------------------------------------
__global__ void k_prep(const float* __restrict__ emb) {
    int k = blockIdx.x, t = threadIdx.x;
    if (k == 0 && t == 0) g_loss = 0.0;

    __shared__ double red[256];
    float v = emb[k * CDIM + t];
    red[t] = (double)v * (double)v;
    __syncthreads();
    #pragma unroll
    for (int s = 128; s > 0; s >>= 1) { if (t < s) red[t] += red[t + s]; __syncthreads(); }
    __shared__ float sDen;
    if (t == 0) {
        float n2 = (float)red[0];
        float n  = sqrtf(n2);
        float den = fmaxf(n, 1e-12f);
        g_en[k] = den; g_en2[k] = n2; sDen = den;
    }
    __syncthreads();
    float wn = v / sDen;
    g_wn [k * CDIM + t]   = wn;
    g_wnT[t * KCODES + k] = wn;

    red[t] = (double)wn * (double)wn;
    __syncthreads();
    #pragma unroll
    for (int s = 128; s > 0; s >>= 1) { if (t < s) red[t] += red[t + s]; __syncthreads(); }
    if (t == 0) g_wn2[k] = (float)red[0];
}

// ---------------------------------------------------------------------------
// Kernel B: normalize z along W (ref-emulating), write zf [N][C] and zfT [C][N].
// Normalization done ONCE in smem via Markstein div (bit-equal to '/'),
// eliminating the 33M-IEEE-division hot spot.
// ---------------------------------------------------------------------------
__global__ void k_znorm(const float* __restrict__ z) {
    __shared__ float tile[64][65];
    __shared__ float den[64];
    __shared__ float rcp[64];
    int bh = blockIdx.x;
    int b = bh >> 6, h = bh & 63;
    int t = threadIdx.x;
    long n0 = (long)bh * 64;

    for (int c0 = 0; c0 < CDIM; c0 += 64) {
        for (int i = t; i < 4096; i += 256) {
            int r = i >> 6, w = i & 63;
            tile[r][w] = z[(((long)b * CDIM + (c0 + r)) * HW + h) * HW + w];
        }
        __syncthreads();
        if (t < 64) {
            double s = 0.0;
            #pragma unroll
            for (int w = 0; w < 64; w++) { double v = (double)tile[t][w]; s += v * v; }
            float d = fmaxf(sqrtf((float)s), 1e-12f);
            den[t] = d;
            rcp[t] = 1.0f / d;          // one true division per row
        }
        __syncthreads();
        // normalize in place (Markstein: bitwise == tile/den)
        for (int i = t; i < 4096; i += 256) {
            int r = i >> 6, w = i & 63;
            tile[r][w] = div_rn(tile[r][w], den[r], rcp[r]);
        }
        __syncthreads();
        // zf [N][C]
        for (int i = t; i < 4096; i += 256) {
            int w = i >> 6, cc = i & 63;
            g_zf[(n0 + w) * CDIM + c0 + cc] = tile[cc][w];
        }
        // zfT [C][N]
        for (int i = t; i < 4096; i += 256) {
            int cc = i >> 6, w = i & 63;
            g_zfT[(long)(c0 + cc) * NQ + n0 + w] = tile[cc][w];
        }
        __syncthreads();
    }
}

// ---------------------------------------------------------------------------
// Dummy: shifts ncu's capture window (4th launch) onto k_znorm this round
// ---------------------------------------------------------------------------
__global__ void k_sync_marker() { if (threadIdx.x == 1024) g_loss = -1.0; }

// ---------------------------------------------------------------------------
// Kernel C: fp32x2 GEMM screen, 2 CTAs/SM, 3-stage cp.async on A AND B.
// (unchanged from R9: profiled 757us)
// ---------------------------------------------------------------------------
__global__ void __launch_bounds__(256, 2) k_gemm_argmax() {
    extern __shared__ float smem[];
    float* s_bv   = smem + SBV_OFF / 4;
    int*   s_bi   = (int*)(smem + SBI_OFF / 4);
    int*   s_cnt  = (int*)(smem + SCNT_OFF / 4);
    int*   s_cand = (int*)(smem + SCAND_OFF / 4);

    const int t  = threadIdx.x;
    const int tx = t & 15;
    const int ty = t >> 4;
    const int n0 = blockIdx.x * MT;

    if (t < MT) { s_bv[t] = -3.0e38f; s_bi[t] = 0; s_cnt[t] = 0; }

    const uint32_t smb = smem_u32(smem);
    const int r0 = t >> 5,        c0 = (t & 31) * 16;
    const int r1 = (t >> 5) + 8,  c1 = (t & 31) * 16;

    #define KICK_TILE(bt_) do {                                                   \
        const int ch_ = (bt_) >> 4, kt_ = (bt_) & 15;                             \
        const int buf_ = (bt_) % 3;                                               \
        const uint32_t ab = smb + (uint32_t)(SMA_OFF + buf_ * 8192);              \
        const uint32_t bb = smb + (uint32_t)(SMB_OFF + buf_ * 8192);              \
        cpasync16(ab + (uint32_t)(r0 * 512 + c0),                                 \
                  g_zfT + (size_t)(kt_ * KT + r0) * NQ + n0 + (c0 >> 2));         \
        cpasync16(ab + (uint32_t)(r1 * 512 + c1),                                 \
                  g_zfT + (size_t)(kt_ * KT + r1) * NQ + n0 + (c1 >> 2));         \
        cpasync16(bb + (uint32_t)(r0 * 512 + c0),                                 \
                  g_wnT + (size_t)(kt_ * KT + r0) * KCODES + ch_ * NTC + (c0 >> 2)); \
        cpasync16(bb + (uint32_t)(r1 * 512 + c1),                                 \
                  g_wnT + (size_t)(kt_ * KT + r1) * KCODES + ch_ * NTC + (c1 >> 2)); \
    } while (0)

    KICK_TILE(0); CP_COMMIT();
    KICK_TILE(1); CP_COMMIT();

    u64 acc[8][4];

    for (int bt = 0; bt < NTILES; bt++) {
        CP_WAIT_1();
        __syncthreads();

        if (bt + 2 < NTILES) { KICK_TILE(bt + 2); }
        CP_COMMIT();

        const int kt  = bt & 15;
        const int buf = bt % 3;
        const float* Ab = smem + (SMA_OFF / 4) + buf * 2048;
        const float* Bb = smem + (SMB_OFF / 4) + buf * 2048;

        if (kt == 0) {
            #pragma unroll
            for (int i = 0; i < 8; i++)
                #pragma unroll
                for (int j = 0; j < 4; j++) acc[i][j] = 0ull;
        }

        #pragma unroll
        for (int kk = 0; kk < KT; kk++) {
            const float* Ak = Ab + kk * MT;
            const float* Bk = Bb + kk * NTC;
            u64 b2[4];
            #pragma unroll
            for (int j = 0; j < 4; j++)
                b2[j] = *(const u64*)(Bk + tx * 8 + 2 * j);
            float4 av0 = *(const float4*)(Ak + ty * 8);
            float4 av1 = *(const float4*)(Ak + ty * 8 + 4);
            float av[8] = {av0.x, av0.y, av0.z, av0.w, av1.x, av1.y, av1.z, av1.w};
            #pragma unroll
            for (int i = 0; i < 8; i++) {
                u64 a2 = pack_dup(av[i]);
                #pragma unroll
                for (int j = 0; j < 4; j++)
                    ffma2(acc[i][j], a2, b2[j]);
            }
        }

        if (kt == 15) {
            const int code0 = (bt >> 4) * NTC;
            #pragma unroll
            for (int i = 0; i < 8; i++) {
                float bv = -3.0e38f;
                int   bj = 0;
                #pragma unroll
                for (int j = 0; j < 4; j++) {
                    float2 p = unpk(acc[i][j]);
                    if (p.x > bv) { bv = p.x; bj = 2 * j; }
                    if (p.y > bv) { bv = p.y; bj = 2 * j + 1; }
                }
                int bc = code0 + tx * 8 + bj;
                #pragma unroll
                for (int off = 8; off > 0; off >>= 1) {
                    float ov = __shfl_xor_sync(0xFFFFFFFFu, bv, off, 16);
                    int   oc = __shfl_xor_sync(0xFFFFFFFFu, bc, off, 16);
                    if (ov > bv || (ov == bv && oc < bc)) { bv = ov; bc = oc; }
                }
                if (tx == 0) {
                    int row = ty * 8 + i;
                    if (bv > s_bv[row]) { s_bv[row] = bv; s_bi[row] = bc; }
                }
            }
            #pragma unroll
            for (int i = 0; i < 8; i++) {
                int row = ty * 8 + i;
                float thr = s_bv[row] - MARGIN;
                #pragma unroll
                for (int j = 0; j < 4; j++) {
                    float2 p = unpk(acc[i][j]);
                    if (p.x >= thr) {
                        int pos = atomicAdd(&s_cnt[row], 1);
                        if (pos < CAND_CAP) s_cand[row * CAND_CAP + pos] = code0 + tx * 8 + 2 * j;
                    }
                    if (p.y >= thr) {
                        int pos = atomicAdd(&s_cnt[row], 1);
                        if (pos < CAND_CAP) s_cand[row * CAND_CAP + pos] = code0 + tx * 8 + 2 * j + 1;
                    }
                }
            }
        }
    }

    __syncthreads();
    if (t < MT) {
        int n = n0 + t;
        g_bi[n] = s_bi[t];
        g_bd[n] = s_bv[t];
        int cnt = s_cnt[t];
        g_ncand[n] = cnt;
        int m = cnt < CAND_CAP ? cnt : CAND_CAP;
        for (int c = 0; c < m; c++) g_cand[n * CAND_CAP + c] = s_cand[t * CAND_CAP + c];
    }
    CP_WAIT_0();
    #undef KICK_TILE
}

// ---------------------------------------------------------------------------
// Kernel C2: exact re-ranking (fp64), emulating reference arithmetic.
// ---------------------------------------------------------------------------
__global__ void k_refine(float* __restrict__ out_idx) {
    int warp = (blockIdx.x * blockDim.x + threadIdx.x) >> 5;
    int lane = threadIdx.x & 31;
    __shared__ double s_loss;
    if (threadIdx.x == 0) s_loss = 0.0;
    __syncthreads();

    if (warp < NQ) {
        int n = warp;
        int cnt = g_ncand[n];
        int bi; float bd;
        if (cnt <= 1) {
            bi = g_bi[n]; bd = g_bd[n];
        } else {
            float zr[8];
            #pragma unroll
            for (int m = 0; m < 8; m++) zr[m] = g_zf[(long)n * CDIM + lane + 32 * m];
            double z2 = 0.0;
            #pragma unroll
            for (int m = 0; m < 8; m++) z2 += (double)zr[m] * (double)zr[m];
            #pragma unroll
            for (int off = 16; off > 0; off >>= 1)
                z2 += __shfl_xor_sync(0xFFFFFFFFu, z2, off);
            float zf2f = (float)z2;

            bool overflow = (cnt > CAND_CAP);
            int ncand = overflow ? KCODES : cnt;
            float dmin = 3.4e38f; int kmin = 0x7FFFFFFF; float bestdot = 0.0f;
            for (int ci = 0; ci < ncand; ci++) {
                int k = overflow ? ci : g_cand[n * CAND_CAP + ci];
                double dot = 0.0;
                const float* wrow = g_wn + (long)k * CDIM;
                #pragma unroll
                for (int m = 0; m < 8; m++)
                    dot += (double)zr[m] * (double)wrow[lane + 32 * m];
                #pragma unroll
                for (int off = 16; off > 0; off >>= 1)
                    dot += __shfl_xor_sync(0xFFFFFFFFu, dot, off);
                float dotf = (float)dot;
                float d = (zf2f + g_wn2[k]) - 2.0f * dotf;
                if (d < dmin || (d == dmin && k < kmin)) { dmin = d; kmin = k; bestdot = dotf; }
            }
            bi = kmin; bd = bestdot;
        }
        if (lane == 0) {
            g_bi[n] = bi;
            out_idx[n] = (float)bi;
            atomicAdd(&s_loss, (double)g_en2[bi] - 2.0 * (double)bd * (double)g_en[bi]);
        }
    }
    __syncthreads();
    if (threadIdx.x == 0) atomicAdd(&g_loss, s_loss);
}

// ---------------------------------------------------------------------------
// Kernel D: gather z_q = embedding[idx], transpose back to [B,C,H,W]
// ---------------------------------------------------------------------------
__global__ void k_gather(const float* __restrict__ emb, float* __restrict__ out) {
    __shared__ int   sIdx[64];
    __shared__ float es[64][129];
    int bh = blockIdx.x;
    int b = bh >> 6, h = bh & 63;
    int t = threadIdx.x;
    long n0 = (long)bh * 64;

    if (t < 64) sIdx[t] = g_bi[n0 + t];
    __syncthreads();

    for (int c0 = 0; c0 < CDIM; c0 += 128) {
        for (int i = t; i < 64 * 128; i += 256) {
            int s = i >> 7, cc = i & 127;
            es[s][cc] = emb[(long)sIdx[s] * CDIM + c0 + cc];
        }
        __syncthreads();
        for (int i = t; i < 64 * 128; i += 256) {
            int cc = i >> 6, w = i & 63;
            out[(((long)b * CDIM + (c0 + cc)) * HW + h) * HW + w] = es[w][cc];
        }
        __syncthreads();
    }
}

// ---------------------------------------------------------------------------
// Kernel E: finalize loss. Sum_n ||zf_n||^2 == 262144 exactly.
// ---------------------------------------------------------------------------
__global__ void k_loss(float* __restrict__ out_loss) {
    double S = g_loss + 262144.0;
    out_loss[0] = (float)(1.25 * S / (double)ZQ_ELEMS);
}

// ---------------------------------------------------------------------------
extern "C" void kernel_launch(void* const* d_in, const int* in_sizes, int n_in,
                              void* d_out, int out_size) {
    const float* z   = (const float*)d_in[0];
    const float* emb = (const float*)d_in[1];
    float* out = (float*)d_out;

    cudaFuncSetAttribute(k_gemm_argmax, cudaFuncAttributeMaxDynamicSharedMemorySize, SM_TOTAL);

    k_prep<<<KCODES, 256>>>(emb);          // 1
    k_sync_marker<<<1, 32>>>();            // 2
    k_sync_marker<<<1, 32>>>();            // 3
    k_znorm<<<BQ * HW, 256>>>(z);          // 4  <- profiled this round
    k_gemm_argmax<<<NQ / MT, 256, SM_TOTAL>>>();   // 5
    k_refine<<<NQ / 8, 256>>>(out + ZQ_ELEMS);     // 6
    k_gather<<<BQ * HW, 256>>>(emb, out);          // 7
    k_loss<<<1, 1>>>(out + ZQ_ELEMS + NQ);         // 8
}